// round 16
// baseline (speedup 1.0000x reference)
#include <cuda_runtime.h>
#include <cuda_bf16.h>
#include <cstdint>
#include <math.h>

#define TOK   256
#define DM    512
#define HEADS 8
#define DK    64
#define NTRM  5             // bf16 terms per input: c1h*xh, c1l*xh, c1h*xl, c2*x^2, c3*x^3
#define GK    (DM * NTRM)   // 2560
#define KSPL  8             // K-split factor
#define KPER  (GK / KSPL)   // 320
#define NCHS  (KPER / 64)   // 5 chunks of 64 per split

// ---------------- device scratch ----------------
__device__ __align__(16) __nv_bfloat16 g_B[4][DM * GK];    // [layer][o][k] K-major
__device__ __align__(16) __nv_bfloat16 g_A[4][TOK * GK];   // [layer][n][k]
__device__ __align__(16) float g_qp[TOK * DM];
__device__ __align__(16) float g_kp[TOK * DM];
__device__ __align__(16) float g_vp[TOK * DM];

// ---------------- PTX helpers ----------------
__device__ __forceinline__ uint32_t s2u(const void* p) {
    uint32_t a;
    asm("{ .reg .u64 t; cvta.to.shared.u64 t, %1; cvt.u32.u64 %0, t; }" : "=r"(a) : "l"(p));
    return a;
}
__device__ __forceinline__ void cpasync16(uint32_t dst, const void* src) {
    asm volatile("cp.async.cg.shared.global [%0], [%1], 16;" :: "r"(dst), "l"(src));
}
__device__ __forceinline__ void cp_commit() {
    asm volatile("cp.async.commit_group;" ::: "memory");
}
__device__ __forceinline__ void cp_wait1() {
    asm volatile("cp.async.wait_group 1;" ::: "memory");
}
__device__ __forceinline__ void cp_wait0() {
    asm volatile("cp.async.wait_group 0;" ::: "memory");
}
__device__ __forceinline__ void ldsm4(uint32_t* r, uint32_t addr) {
    asm volatile("ldmatrix.sync.aligned.m8n8.x4.shared.b16 {%0,%1,%2,%3}, [%4];"
                 : "=r"(r[0]), "=r"(r[1]), "=r"(r[2]), "=r"(r[3]) : "r"(addr));
}
__device__ __forceinline__ void mma16816(float* c, const uint32_t* a, uint32_t b0, uint32_t b1) {
    asm volatile(
        "mma.sync.aligned.m16n8k16.row.col.f32.bf16.bf16.f32 "
        "{%0,%1,%2,%3}, {%4,%5,%6,%7}, {%8,%9}, {%0,%1,%2,%3};"
        : "+f"(c[0]), "+f"(c[1]), "+f"(c[2]), "+f"(c[3])
        : "r"(a[0]), "r"(a[1]), "r"(a[2]), "r"(a[3]), "r"(b0), "r"(b1));
}
__device__ __forceinline__ void redv2(float* p, float a, float b) {
    asm volatile("red.global.add.v2.f32 [%0], {%1, %2};" :: "l"(p), "f"(a), "f"(b) : "memory");
}

// tiny-arg sin/cos, |t| <= 0.032 -> error < 5e-9
__device__ __forceinline__ float sin_small(float t) {
    float t2 = t * t;
    return t * fmaf(t2, fmaf(t2, 1.f / 120.f, -1.f / 6.f), 1.f);
}
__device__ __forceinline__ float cos_small(float t) {
    float t2 = t * t;
    return fmaf(t2, fmaf(t2, 1.f / 24.f, -0.5f), 1.f);
}

// ---------------- fused prep: coefficients + bias-init + qkv expansion ----------------
__global__ void __launch_bounds__(256) fused_prep(
    const float* __restrict__ q, const float* __restrict__ k, const float* __restrict__ v,
    const float* __restrict__ wq, const float* __restrict__ bq,
    const float* __restrict__ wk, const float* __restrict__ bk,
    const float* __restrict__ wv, const float* __restrict__ bv_,
    const float* __restrict__ wo, const float* __restrict__ bo,
    float* __restrict__ dout)
{
    int b = blockIdx.x, tid = threadIdx.x;
    __shared__ __align__(16) __nv_bfloat16 st[256 * NTRM];

    if (b < 4096) {
        int l = b >> 10, blk = b & 1023;
        const float* w  = (l == 0) ? wq : (l == 1) ? wk : (l == 2) ? wv : wo;
        const float* bb = (l == 0) ? bq : (l == 1) ? bk : (l == 2) ? bv_ : bo;
        int idx = blk * 256 + tid;
        int o = idx >> 9, i = idx & 511;
        float w0 = w[o * 1024 + i * 2];
        float w1 = w[o * 1024 + i * 2 + 1];
        float bv = bb[o * 513 + i];
        float sb = sin_small(bv), cb = cos_small(bv);
        float c1 = w0 * cb * w1;
        __nv_bfloat16 ch = __float2bfloat16(c1);
        __nv_bfloat16 cl = __float2bfloat16(c1 - __bfloat162float(ch));
        float w12 = w1 * w1, w13 = w12 * w1;
        __nv_bfloat16* d = &st[tid * NTRM];
        d[0] = ch;
        d[1] = cl;
        d[2] = ch;
        d[3] = __float2bfloat16(-w0 * sb * w12 * 0.5f);
        d[4] = __float2bfloat16(-w0 * cb * w13 * (1.f / 6.f));
        __syncthreads();
        const uint4* ss = (const uint4*)st;
        uint4* dd = (uint4*)(&g_B[l][(size_t)blk * 256 * NTRM]);
        for (int u = tid; u < 256 * NTRM / 8; u += 256) dd[u] = ss[u];
    } else if (b < 6144) {
        int bi = b - 4096;
        int l = bi >> 9, o = bi & 511;
        const float* w  = (l == 0) ? wq : (l == 1) ? wk : (l == 2) ? wv : wo;
        const float* bb = (l == 0) ? bq : (l == 1) ? bk : (l == 2) ? bv_ : bo;
        float s = w[o * 1024 + tid * 2] * sin_small(bb[o * 513 + tid]) +
                  w[o * 1024 + (tid + 256) * 2] * sin_small(bb[o * 513 + tid + 256]);
        s += __shfl_xor_sync(0xffffffffu, s, 16);
        s += __shfl_xor_sync(0xffffffffu, s, 8);
        s += __shfl_xor_sync(0xffffffffu, s, 4);
        s += __shfl_xor_sync(0xffffffffu, s, 2);
        s += __shfl_xor_sync(0xffffffffu, s, 1);
        __shared__ float red[8];
        if ((tid & 31) == 0) red[tid >> 5] = s;
        __syncthreads();
        __shared__ float bval;
        if (tid == 0) {
            bval = bb[o * 513 + 512] + red[0] + red[1] + red[2] + red[3] +
                   red[4] + red[5] + red[6] + red[7];
        }
        __syncthreads();
        float* dst = (l == 0) ? g_qp : (l == 1) ? g_kp : (l == 2) ? g_vp : dout;
        dst[tid * DM + o] = bval;    // broadcast bias into all 256 rows
    } else {
        int ei = b - 6144;
        int z = ei >> 9, blk = ei & 511;
        const float* x = (z == 0) ? q : (z == 1) ? k : v;
        int idx = blk * 256 + tid;
        float vv = x[idx];
        __nv_bfloat16 ah = __float2bfloat16(vv);
        float al = vv - __bfloat162float(ah);
        float v2 = vv * vv, v3 = v2 * vv;
        __nv_bfloat16* d = &st[tid * NTRM];
        d[0] = ah;
        d[1] = ah;
        d[2] = __float2bfloat16(al);
        d[3] = __float2bfloat16(v2);
        d[4] = __float2bfloat16(v3);
        __syncthreads();
        const uint4* ss = (const uint4*)st;
        uint4* dd = (uint4*)(&g_A[z][(size_t)blk * 256 * NTRM]);
        for (int u = tid; u < 256 * NTRM / 8; u += 256) dd[u] = ss[u];
    }
}

// ---------------- mma.sync GEMM, 8 warps (2x4), 64x64 tile, red.v2 epilogue ----------------
#define BSTRIDE 72
#define ROWB    (BSTRIDE * 2)         // 144 bytes
#define TILEB   (64 * ROWB)           // 9216 bytes

__device__ __forceinline__ void stage(uint32_t sA, uint32_t sB,
                                      const __nv_bfloat16* Ab, const __nv_bfloat16* Bb,
                                      int kofs, int tid)
{
#pragma unroll
    for (int j = 0; j < 2; j++) {
        int c = tid + j * 256;
        int r = c >> 3, q = c & 7;
        cpasync16(sA + r * ROWB + q * 16, Ab + r * GK + kofs + q * 8);
        cpasync16(sB + r * ROWB + q * 16, Bb + r * GK + kofs + q * 8);
    }
    cp_commit();
}

__global__ void __launch_bounds__(256) gemm_kernel(float* __restrict__ ext_out, int layer0)
{
    __shared__ __align__(16) char smem[2][2 * TILEB];
    uint32_t sb0 = s2u(smem);
    int tid = threadIdx.x, wid = tid >> 5, lane = tid & 31;
    int wm = wid >> 2, wn = wid & 3;          // 2 x 4 warp grid; warp tile 32x16
    int z = blockIdx.z;
    int lrel = z >> 3, split = z & 7;
    int layer = layer0 + lrel;
    const __nv_bfloat16* A = g_A[layer];
    const __nv_bfloat16* B = g_B[layer];
    float* out = (layer == 0) ? g_qp : (layer == 1) ? g_kp : (layer == 2) ? g_vp : ext_out;
    int m0 = blockIdx.y * 64, n0 = blockIdx.x * 64;
    int kbase = split * KPER;

    const __nv_bfloat16* Am = A + m0 * GK;
    const __nv_bfloat16* Bn = B + n0 * GK;

    float acc[2][2][4];
#pragma unroll
    for (int mi = 0; mi < 2; mi++)
#pragma unroll
        for (int nj = 0; nj < 2; nj++)
#pragma unroll
            for (int e = 0; e < 4; e++) acc[mi][nj][e] = 0.f;

    uint32_t a_off = (uint32_t)((wm * 32 + (lane & 15)) * ROWB + (lane >> 4) * 16);
    uint32_t b_off = (uint32_t)((wn * 16 + (lane & 15)) * ROWB + (lane >> 4) * 16);

    stage(sb0, sb0 + TILEB, Am, Bn, kbase, tid);
    stage(sb0 + 2 * TILEB, sb0 + 3 * TILEB, Am, Bn, kbase + 64, tid);

    for (int c = 0; c < NCHS; c++) {
        if (c < NCHS - 1) cp_wait1(); else cp_wait0();
        __syncthreads();
        uint32_t base = sb0 + (uint32_t)(c & 1) * (2 * TILEB);
        uint32_t aB = base + a_off;
        uint32_t bB = base + TILEB + b_off;
#pragma unroll
        for (int ks = 0; ks < 4; ks++) {
            uint32_t a0[4], a1[4], br[4];
            ldsm4(a0, aB + ks * 32);
            ldsm4(a1, aB + ks * 32 + 16 * ROWB);
            ldsm4(br, bB + ks * 32);
            mma16816(acc[0][0], a0, br[0], br[2]);
            mma16816(acc[0][1], a0, br[1], br[3]);
            mma16816(acc[1][0], a1, br[0], br[2]);
            mma16816(acc[1][1], a1, br[1], br[3]);
        }
        __syncthreads();
        if (c + 2 < NCHS)
            stage(sb0 + (uint32_t)(c & 1) * (2 * TILEB),
                  sb0 + (uint32_t)(c & 1) * (2 * TILEB) + TILEB,
                  Am, Bn, kbase + (c + 2) * 64, tid);
    }

    // epilogue: vector red accumulate into bias-initialized output
    int rbase = m0 + wm * 32 + (lane >> 2);
    int cbase = n0 + wn * 16 + (lane & 3) * 2;
#pragma unroll
    for (int mi = 0; mi < 2; mi++) {
#pragma unroll
        for (int nj = 0; nj < 2; nj++) {
            int col = cbase + nj * 8;
            int r0 = rbase + mi * 16;
            redv2(&out[r0 * DM + col], acc[mi][nj][0], acc[mi][nj][1]);
            redv2(&out[(r0 + 8) * DM + col], acc[mi][nj][2], acc[mi][nj][3]);
        }
    }
}

// ---------------- attention: broadcast-friendly 3-phase, 128 CTAs x 512 threads ----------------
#define KROW 68
#define PROW 132
#define QTILE 16

__global__ void __launch_bounds__(512, 1) attn_kernel()
{
    extern __shared__ float sm[];
    float* Ks = sm;                          // [128][KROW]
    float* Vs = sm + 128 * KROW;             // [128][KROW]
    float* Qs = sm + 2 * 128 * KROW;         // [QTILE][KROW]
    float* Ps = sm + (2 * 128 + QTILE) * KROW;  // [QTILE][PROW]  (S, then P)

    int b = blockIdx.z, h = blockIdx.y, q0 = blockIdx.x * QTILE;
    int tid = threadIdx.x;
    int wid = tid >> 5, lane = tid & 31;

    const float* kbase = g_kp + b * 128 * DM + h * DK;
    const float* vbase = g_vp + b * 128 * DM + h * DK;
    const float* qbase = g_qp + (b * 128 + q0) * DM + h * DK;

    for (int e = tid; e < 128 * (DK / 4); e += 512) {
        int s = e >> 4, c = (e & 15) << 2;
        *(float4*)&Ks[s * KROW + c] = *(const float4*)&kbase[s * DM + c];
        *(float4*)&Vs[s * KROW + c] = *(const float4*)&vbase[s * DM + c];
    }
    if (tid < QTILE * (DK / 4)) {
        int s = tid >> 4, c = (tid & 15) << 2;
        *(float4*)&Qs[s * KROW + c] = *(const float4*)&qbase[s * DM + c];
    }
    __syncthreads();

    // ---- phase 1: warp w computes S[all 16 q][k in w*8..w*8+7] ----
    {
        int q = lane >> 1;
        int kk = wid * 8 + (lane & 1) * 4;
        const float* qr = &Qs[q * KROW];
        float acc[4] = {0.f, 0.f, 0.f, 0.f};
#pragma unroll
        for (int c4 = 0; c4 < 16; c4++) {
            float4 qa = *(const float4*)&qr[c4 * 4];
#pragma unroll
            for (int j = 0; j < 4; j++) {
                float4 kv = *(const float4*)&Ks[(kk + j) * KROW + c4 * 4];
                acc[j] = fmaf(qa.x, kv.x, acc[j]);
                acc[j] = fmaf(qa.y, kv.y, acc[j]);
                acc[j] = fmaf(qa.z, kv.z, acc[j]);
                acc[j] = fmaf(qa.w, kv.w, acc[j]);
            }
        }
#pragma unroll
        for (int j = 0; j < 4; j++)
            Ps[q * PROW + kk + j] = acc[j] * 0.125f;
    }
    __syncthreads();

    // ---- phase 1b: softmax, warp r handles row r ----
    {
        int r = wid;
        float s[4];
#pragma unroll
        for (int j = 0; j < 4; j++) s[j] = Ps[r * PROW + lane + 32 * j];
        float m0 = fmaxf(fmaxf(s[0], s[1]), fmaxf(s[2], s[3]));
#pragma unroll
        for (int msk = 16; msk >= 1; msk >>= 1)
            m0 = fmaxf(m0, __shfl_xor_sync(0xffffffffu, m0, msk));
        float sum = 0.f;
#pragma unroll
        for (int j = 0; j < 4; j++) { s[j] = __expf(s[j] - m0); sum += s[j]; }
#pragma unroll
        for (int msk = 16; msk >= 1; msk >>= 1)
            sum += __shfl_xor_sync(0xffffffffu, sum, msk);
        float inv = 1.0f / sum;
#pragma unroll
        for (int j = 0; j < 4; j++) Ps[r * PROW + lane + 32 * j] = s[j] * inv;
    }
    __syncthreads();

    // ---- phase 2: warp w computes O[all 16 q][d in w*4..w*4+3] ----
    {
        int q = lane >> 1, dh = lane & 1;
        int dcol = wid * 4 + dh * 2;
        const float* pr = &Ps[q * PROW];
        float ox = 0.f, oy = 0.f;
#pragma unroll 4
        for (int kb = 0; kb < 32; kb++) {
            float4 p4 = *(const float4*)&pr[kb * 4];
            float2 v0 = *(const float2*)&Vs[(kb * 4 + 0) * KROW + dcol];
            float2 v1 = *(const float2*)&Vs[(kb * 4 + 1) * KROW + dcol];
            float2 v2 = *(const float2*)&Vs[(kb * 4 + 2) * KROW + dcol];
            float2 v3 = *(const float2*)&Vs[(kb * 4 + 3) * KROW + dcol];
            ox = fmaf(p4.x, v0.x, ox); oy = fmaf(p4.x, v0.y, oy);
            ox = fmaf(p4.y, v1.x, ox); oy = fmaf(p4.y, v1.y, oy);
            ox = fmaf(p4.z, v2.x, ox); oy = fmaf(p4.z, v2.y, oy);
            ox = fmaf(p4.w, v3.x, ox); oy = fmaf(p4.w, v3.y, oy);
        }

        // fused Taylor-feature epilogue for the 2 output values
        int n = b * 128 + q0 + q;
        int i0 = h * DK + dcol;               // even -> 4B-aligned dst
        float vals[2] = {ox, oy};
        __align__(4) __nv_bfloat16 tmp[10];
#pragma unroll
        for (int c = 0; c < 2; c++) {
            float v = vals[c];
            __nv_bfloat16 ah = __float2bfloat16(v);
            float al = v - __bfloat162float(ah);
            float v2s = v * v, v3s = v2s * v;
            tmp[c * 5 + 0] = ah;
            tmp[c * 5 + 1] = ah;
            tmp[c * 5 + 2] = __float2bfloat16(al);
            tmp[c * 5 + 3] = __float2bfloat16(v2s);
            tmp[c * 5 + 4] = __float2bfloat16(v3s);
        }
        uint32_t* dp = (uint32_t*)&g_A[3][(size_t)n * GK + (size_t)i0 * NTRM];
        const uint32_t* ts = (const uint32_t*)tmp;
#pragma unroll
        for (int u = 0; u < 5; u++) dp[u] = ts[u];
    }
}

// ---------------- launch ----------------
extern "C" void kernel_launch(void* const* d_in, const int* in_sizes, int n_in,
                              void* d_out, int out_size)
{
    const float* q  = (const float*)d_in[0];
    const float* k  = (const float*)d_in[1];
    const float* v  = (const float*)d_in[2];
    const float* wq = (const float*)d_in[3];
    const float* bq = (const float*)d_in[4];
    const float* wk = (const float*)d_in[5];
    const float* bk = (const float*)d_in[6];
    const float* wv = (const float*)d_in[7];
    const float* bv = (const float*)d_in[8];
    const float* wo = (const float*)d_in[9];
    const float* bo = (const float*)d_in[10];
    float* out = (float*)d_out;

    size_t attn_smem = (size_t)((2 * 128 + QTILE) * KROW + QTILE * PROW) * sizeof(float); // ~83KB
    cudaFuncSetAttribute(attn_kernel, cudaFuncAttributeMaxDynamicSharedMemorySize,
                         (int)attn_smem);

    // 1) fused: coefficients + bias-init of all destinations (incl. d_out) + qkv expansion
    fused_prep<<<7680, 256>>>(q, k, v, wq, bq, wk, bk, wv, bv, wo, bo, out);

    // 2) q/k/v projections: K-split GEMMs, red.v2 accumulate into bias-initialized buffers
    gemm_kernel<<<dim3(8, 4, 24), 256>>>(out, 0);

    // 3) attention (128 CTAs x 16 warps, broadcast-friendly) + fused expansion into g_A[3]
    attn_kernel<<<dim3(8, HEADS, 2), 512, attn_smem>>>();

    // 4) final projection GEMM, red.v2 accumulate -> d_out
    gemm_kernel<<<dim3(8, 4, 8), 256>>>(out, 3);
}

// round 17
// speedup vs baseline: 1.1954x; 1.1954x over previous
#include <cuda_runtime.h>
#include <cuda_bf16.h>
#include <cstdint>
#include <math.h>

#define TOK   256
#define DM    512
#define HEADS 8
#define DK    64
#define NTRM  4             // bf16 terms per input: c1h*xh, c1l*xh, c1h*xl, c2*x^2
#define GK    (DM * NTRM)   // 2048
#define KSPL  8             // K-split factor
#define KPER  (GK / KSPL)   // 256
#define NCHS  (KPER / 64)   // 4 chunks of 64 per split

// ---------------- device scratch ----------------
__device__ __align__(16) __nv_bfloat16 g_B[4][DM * GK];    // [layer][o][k] K-major
__device__ __align__(16) __nv_bfloat16 g_A[4][TOK * GK];   // [layer][n][k]
__device__ __align__(16) float g_qp[TOK * DM];
__device__ __align__(16) float g_kp[TOK * DM];
__device__ __align__(16) float g_vp[TOK * DM];

// ---------------- PTX helpers ----------------
__device__ __forceinline__ uint32_t s2u(const void* p) {
    uint32_t a;
    asm("{ .reg .u64 t; cvta.to.shared.u64 t, %1; cvt.u32.u64 %0, t; }" : "=r"(a) : "l"(p));
    return a;
}
__device__ __forceinline__ void cpasync16(uint32_t dst, const void* src) {
    asm volatile("cp.async.cg.shared.global [%0], [%1], 16;" :: "r"(dst), "l"(src));
}
__device__ __forceinline__ void cp_commit() {
    asm volatile("cp.async.commit_group;" ::: "memory");
}
__device__ __forceinline__ void cp_wait1() {
    asm volatile("cp.async.wait_group 1;" ::: "memory");
}
__device__ __forceinline__ void cp_wait0() {
    asm volatile("cp.async.wait_group 0;" ::: "memory");
}
__device__ __forceinline__ void ldsm4(uint32_t* r, uint32_t addr) {
    asm volatile("ldmatrix.sync.aligned.m8n8.x4.shared.b16 {%0,%1,%2,%3}, [%4];"
                 : "=r"(r[0]), "=r"(r[1]), "=r"(r[2]), "=r"(r[3]) : "r"(addr));
}
__device__ __forceinline__ void mma16816(float* c, const uint32_t* a, uint32_t b0, uint32_t b1) {
    asm volatile(
        "mma.sync.aligned.m16n8k16.row.col.f32.bf16.bf16.f32 "
        "{%0,%1,%2,%3}, {%4,%5,%6,%7}, {%8,%9}, {%0,%1,%2,%3};"
        : "+f"(c[0]), "+f"(c[1]), "+f"(c[2]), "+f"(c[3])
        : "r"(a[0]), "r"(a[1]), "r"(a[2]), "r"(a[3]), "r"(b0), "r"(b1));
}
__device__ __forceinline__ void redv2(float* p, float a, float b) {
    asm volatile("red.global.add.v2.f32 [%0], {%1, %2};" :: "l"(p), "f"(a), "f"(b) : "memory");
}

// tiny-arg sin/cos, |t| <= 0.032 -> error < 5e-9
__device__ __forceinline__ float sin_small(float t) {
    float t2 = t * t;
    return t * fmaf(t2, fmaf(t2, 1.f / 120.f, -1.f / 6.f), 1.f);
}
__device__ __forceinline__ float cos_small(float t) {
    float t2 = t * t;
    return fmaf(t2, fmaf(t2, 1.f / 24.f, -0.5f), 1.f);
}

// ---------------- fused prep: coefficients + bias-init + qkv expansion ----------------
__global__ void __launch_bounds__(256) fused_prep(
    const float* __restrict__ q, const float* __restrict__ k, const float* __restrict__ v,
    const float* __restrict__ wq, const float* __restrict__ bq,
    const float* __restrict__ wk, const float* __restrict__ bk,
    const float* __restrict__ wv, const float* __restrict__ bv_,
    const float* __restrict__ wo, const float* __restrict__ bo,
    float* __restrict__ dout)
{
    int b = blockIdx.x, tid = threadIdx.x;
    __shared__ __align__(16) __nv_bfloat16 st[256 * NTRM];

    if (b < 4096) {
        int l = b >> 10, blk = b & 1023;
        const float* w  = (l == 0) ? wq : (l == 1) ? wk : (l == 2) ? wv : wo;
        const float* bb = (l == 0) ? bq : (l == 1) ? bk : (l == 2) ? bv_ : bo;
        int idx = blk * 256 + tid;
        int o = idx >> 9, i = idx & 511;
        float w0 = w[o * 1024 + i * 2];
        float w1 = w[o * 1024 + i * 2 + 1];
        float bv = bb[o * 513 + i];
        float sb = sin_small(bv), cb = cos_small(bv);
        float c1 = w0 * cb * w1;
        __nv_bfloat16 ch = __float2bfloat16(c1);
        __nv_bfloat16 cl = __float2bfloat16(c1 - __bfloat162float(ch));
        float w12 = w1 * w1;
        __nv_bfloat16* d = &st[tid * NTRM];
        d[0] = ch;
        d[1] = cl;
        d[2] = ch;
        d[3] = __float2bfloat16(-w0 * sb * w12 * 0.5f);
        __syncthreads();
        const uint4* ss = (const uint4*)st;
        uint4* dd = (uint4*)(&g_B[l][(size_t)blk * 256 * NTRM]);
        for (int u = tid; u < 256 * NTRM / 8; u += 256) dd[u] = ss[u];
    } else if (b < 6144) {
        int bi = b - 4096;
        int l = bi >> 9, o = bi & 511;
        const float* w  = (l == 0) ? wq : (l == 1) ? wk : (l == 2) ? wv : wo;
        const float* bb = (l == 0) ? bq : (l == 1) ? bk : (l == 2) ? bv_ : bo;
        float s = w[o * 1024 + tid * 2] * sin_small(bb[o * 513 + tid]) +
                  w[o * 1024 + (tid + 256) * 2] * sin_small(bb[o * 513 + tid + 256]);
        s += __shfl_xor_sync(0xffffffffu, s, 16);
        s += __shfl_xor_sync(0xffffffffu, s, 8);
        s += __shfl_xor_sync(0xffffffffu, s, 4);
        s += __shfl_xor_sync(0xffffffffu, s, 2);
        s += __shfl_xor_sync(0xffffffffu, s, 1);
        __shared__ float red[8];
        if ((tid & 31) == 0) red[tid >> 5] = s;
        __syncthreads();
        __shared__ float bval;
        if (tid == 0) {
            bval = bb[o * 513 + 512] + red[0] + red[1] + red[2] + red[3] +
                   red[4] + red[5] + red[6] + red[7];
        }
        __syncthreads();
        float* dst = (l == 0) ? g_qp : (l == 1) ? g_kp : (l == 2) ? g_vp : dout;
        dst[tid * DM + o] = bval;    // broadcast bias into all 256 rows
    } else {
        int ei = b - 6144;
        int z = ei >> 9, blk = ei & 511;
        const float* x = (z == 0) ? q : (z == 1) ? k : v;
        int idx = blk * 256 + tid;
        float vv = x[idx];
        __nv_bfloat16 ah = __float2bfloat16(vv);
        float al = vv - __bfloat162float(ah);
        float v2 = vv * vv;
        __nv_bfloat16* d = &st[tid * NTRM];
        d[0] = ah;
        d[1] = ah;
        d[2] = __float2bfloat16(al);
        d[3] = __float2bfloat16(v2);
        __syncthreads();
        const uint4* ss = (const uint4*)st;
        uint4* dd = (uint4*)(&g_A[z][(size_t)blk * 256 * NTRM]);
        for (int u = tid; u < 256 * NTRM / 8; u += 256) dd[u] = ss[u];
    }
}

// ---------------- mma.sync GEMM with K-split, red.v2 accumulate epilogue ----------------
#define BSTRIDE 72
#define ROWB    (BSTRIDE * 2)         // 144 bytes
#define TILEB   (64 * ROWB)           // 9216 bytes

__device__ __forceinline__ void stage(uint32_t sA, uint32_t sB,
                                      const __nv_bfloat16* Ab, const __nv_bfloat16* Bb,
                                      int kofs, int tid)
{
#pragma unroll
    for (int j = 0; j < 4; j++) {
        int c = tid + j * 128;
        int r = c >> 3, q = c & 7;
        cpasync16(sA + r * ROWB + q * 16, Ab + r * GK + kofs + q * 8);
        cpasync16(sB + r * ROWB + q * 16, Bb + r * GK + kofs + q * 8);
    }
    cp_commit();
}

__global__ void __launch_bounds__(128) gemm_kernel(float* __restrict__ ext_out, int layer0)
{
    __shared__ __align__(16) char smem[2][2 * TILEB];
    uint32_t sb0 = s2u(smem);
    int tid = threadIdx.x, wid = tid >> 5, lane = tid & 31;
    int wm = wid >> 1, wn = wid & 1;
    int z = blockIdx.z;
    int lrel = z >> 3, split = z & 7;
    int layer = layer0 + lrel;
    const __nv_bfloat16* A = g_A[layer];
    const __nv_bfloat16* B = g_B[layer];
    float* out = (layer == 0) ? g_qp : (layer == 1) ? g_kp : (layer == 2) ? g_vp : ext_out;
    int m0 = blockIdx.y * 64, n0 = blockIdx.x * 64;
    int kbase = split * KPER;

    const __nv_bfloat16* Am = A + m0 * GK;
    const __nv_bfloat16* Bn = B + n0 * GK;

    float acc[2][4][4];
#pragma unroll
    for (int mi = 0; mi < 2; mi++)
#pragma unroll
        for (int nj = 0; nj < 4; nj++)
#pragma unroll
            for (int e = 0; e < 4; e++) acc[mi][nj][e] = 0.f;

    uint32_t a_off = (uint32_t)((wm * 32 + (lane & 15)) * ROWB + (lane >> 4) * 16);
    uint32_t b_off = (uint32_t)((wn * 32 + (lane & 15)) * ROWB + (lane >> 4) * 16);

    stage(sb0, sb0 + TILEB, Am, Bn, kbase, tid);
    stage(sb0 + 2 * TILEB, sb0 + 3 * TILEB, Am, Bn, kbase + 64, tid);

    for (int c = 0; c < NCHS; c++) {
        if (c < NCHS - 1) cp_wait1(); else cp_wait0();
        __syncthreads();
        uint32_t base = sb0 + (uint32_t)(c & 1) * (2 * TILEB);
        uint32_t aB = base + a_off;
        uint32_t bB = base + TILEB + b_off;
#pragma unroll
        for (int ks = 0; ks < 4; ks++) {
            uint32_t a0[4], a1[4], br0[4], br1[4];
            ldsm4(a0, aB + ks * 32);
            ldsm4(a1, aB + ks * 32 + 16 * ROWB);
            ldsm4(br0, bB + ks * 32);
            ldsm4(br1, bB + ks * 32 + 16 * ROWB);
            mma16816(acc[0][0], a0, br0[0], br0[2]);
            mma16816(acc[0][1], a0, br0[1], br0[3]);
            mma16816(acc[0][2], a0, br1[0], br1[2]);
            mma16816(acc[0][3], a0, br1[1], br1[3]);
            mma16816(acc[1][0], a1, br0[0], br0[2]);
            mma16816(acc[1][1], a1, br0[1], br0[3]);
            mma16816(acc[1][2], a1, br1[0], br1[2]);
            mma16816(acc[1][3], a1, br1[1], br1[3]);
        }
        __syncthreads();
        if (c + 2 < NCHS)
            stage(sb0 + (uint32_t)(c & 1) * (2 * TILEB),
                  sb0 + (uint32_t)(c & 1) * (2 * TILEB) + TILEB,
                  Am, Bn, kbase + (c + 2) * 64, tid);
    }

    // epilogue: vector red accumulate into bias-initialized output
    int rbase = m0 + wm * 32 + (lane >> 2);
    int cbase = n0 + wn * 32 + (lane & 3) * 2;
#pragma unroll
    for (int mi = 0; mi < 2; mi++) {
#pragma unroll
        for (int nj = 0; nj < 4; nj++) {
            int col = cbase + nj * 8;
            int r0 = rbase + mi * 16;
            redv2(&out[r0 * DM + col], acc[mi][nj][0], acc[mi][nj][1]);
            redv2(&out[(r0 + 8) * DM + col], acc[mi][nj][2], acc[mi][nj][3]);
        }
    }
}

// ---------------- attention: broadcast-friendly 3-phase, 128 CTAs x 512 threads ----------------
#define KROW 68
#define PROW 132
#define QTILE 16

__global__ void __launch_bounds__(512, 1) attn_kernel()
{
    extern __shared__ float sm[];
    float* Ks = sm;                          // [128][KROW]
    float* Vs = sm + 128 * KROW;             // [128][KROW]
    float* Qs = sm + 2 * 128 * KROW;         // [QTILE][KROW]
    float* Ps = sm + (2 * 128 + QTILE) * KROW;  // [QTILE][PROW]  (S, then P)

    int b = blockIdx.z, h = blockIdx.y, q0 = blockIdx.x * QTILE;
    int tid = threadIdx.x;
    int wid = tid >> 5, lane = tid & 31;

    const float* kbase = g_kp + b * 128 * DM + h * DK;
    const float* vbase = g_vp + b * 128 * DM + h * DK;
    const float* qbase = g_qp + (b * 128 + q0) * DM + h * DK;

    for (int e = tid; e < 128 * (DK / 4); e += 512) {
        int s = e >> 4, c = (e & 15) << 2;
        *(float4*)&Ks[s * KROW + c] = *(const float4*)&kbase[s * DM + c];
        *(float4*)&Vs[s * KROW + c] = *(const float4*)&vbase[s * DM + c];
    }
    if (tid < QTILE * (DK / 4)) {
        int s = tid >> 4, c = (tid & 15) << 2;
        *(float4*)&Qs[s * KROW + c] = *(const float4*)&qbase[s * DM + c];
    }
    __syncthreads();

    // ---- phase 1: warp w computes S[all 16 q][k in w*8..w*8+7] ----
    {
        int q = lane >> 1;
        int kk = wid * 8 + (lane & 1) * 4;
        const float* qr = &Qs[q * KROW];
        float acc[4] = {0.f, 0.f, 0.f, 0.f};
#pragma unroll
        for (int c4 = 0; c4 < 16; c4++) {
            float4 qa = *(const float4*)&qr[c4 * 4];
#pragma unroll
            for (int j = 0; j < 4; j++) {
                float4 kv = *(const float4*)&Ks[(kk + j) * KROW + c4 * 4];
                acc[j] = fmaf(qa.x, kv.x, acc[j]);
                acc[j] = fmaf(qa.y, kv.y, acc[j]);
                acc[j] = fmaf(qa.z, kv.z, acc[j]);
                acc[j] = fmaf(qa.w, kv.w, acc[j]);
            }
        }
#pragma unroll
        for (int j = 0; j < 4; j++)
            Ps[q * PROW + kk + j] = acc[j] * 0.125f;
    }
    __syncthreads();

    // ---- phase 1b: softmax, warp r handles row r ----
    {
        int r = wid;
        float s[4];
#pragma unroll
        for (int j = 0; j < 4; j++) s[j] = Ps[r * PROW + lane + 32 * j];
        float m0 = fmaxf(fmaxf(s[0], s[1]), fmaxf(s[2], s[3]));
#pragma unroll
        for (int msk = 16; msk >= 1; msk >>= 1)
            m0 = fmaxf(m0, __shfl_xor_sync(0xffffffffu, m0, msk));
        float sum = 0.f;
#pragma unroll
        for (int j = 0; j < 4; j++) { s[j] = __expf(s[j] - m0); sum += s[j]; }
#pragma unroll
        for (int msk = 16; msk >= 1; msk >>= 1)
            sum += __shfl_xor_sync(0xffffffffu, sum, msk);
        float inv = 1.0f / sum;
#pragma unroll
        for (int j = 0; j < 4; j++) Ps[r * PROW + lane + 32 * j] = s[j] * inv;
    }
    __syncthreads();

    // ---- phase 2: warp w computes O[all 16 q][d in w*4..w*4+3] ----
    {
        int q = lane >> 1, dh = lane & 1;
        int dcol = wid * 4 + dh * 2;
        const float* pr = &Ps[q * PROW];
        float ox = 0.f, oy = 0.f;
#pragma unroll 4
        for (int kb = 0; kb < 32; kb++) {
            float4 p4 = *(const float4*)&pr[kb * 4];
            float2 v0 = *(const float2*)&Vs[(kb * 4 + 0) * KROW + dcol];
            float2 v1 = *(const float2*)&Vs[(kb * 4 + 1) * KROW + dcol];
            float2 v2 = *(const float2*)&Vs[(kb * 4 + 2) * KROW + dcol];
            float2 v3 = *(const float2*)&Vs[(kb * 4 + 3) * KROW + dcol];
            ox = fmaf(p4.x, v0.x, ox); oy = fmaf(p4.x, v0.y, oy);
            ox = fmaf(p4.y, v1.x, ox); oy = fmaf(p4.y, v1.y, oy);
            ox = fmaf(p4.z, v2.x, ox); oy = fmaf(p4.z, v2.y, oy);
            ox = fmaf(p4.w, v3.x, ox); oy = fmaf(p4.w, v3.y, oy);
        }

        // fused Taylor-feature epilogue for the 2 output values
        int n = b * 128 + q0 + q;
        int i0 = h * DK + dcol;               // even -> 4B-aligned dst
        float vals[2] = {ox, oy};
        __align__(4) __nv_bfloat16 tmp[8];
#pragma unroll
        for (int c = 0; c < 2; c++) {
            float v = vals[c];
            __nv_bfloat16 ah = __float2bfloat16(v);
            float al = v - __bfloat162float(ah);
            float v2s = v * v;
            tmp[c * 4 + 0] = ah;
            tmp[c * 4 + 1] = ah;
            tmp[c * 4 + 2] = __float2bfloat16(al);
            tmp[c * 4 + 3] = __float2bfloat16(v2s);
        }
        uint32_t* dp = (uint32_t*)&g_A[3][(size_t)n * GK + (size_t)i0 * NTRM];
        const uint32_t* ts = (const uint32_t*)tmp;
#pragma unroll
        for (int u = 0; u < 4; u++) dp[u] = ts[u];
    }
}

// ---------------- launch ----------------
extern "C" void kernel_launch(void* const* d_in, const int* in_sizes, int n_in,
                              void* d_out, int out_size)
{
    const float* q  = (const float*)d_in[0];
    const float* k  = (const float*)d_in[1];
    const float* v  = (const float*)d_in[2];
    const float* wq = (const float*)d_in[3];
    const float* bq = (const float*)d_in[4];
    const float* wk = (const float*)d_in[5];
    const float* bk = (const float*)d_in[6];
    const float* wv = (const float*)d_in[7];
    const float* bv = (const float*)d_in[8];
    const float* wo = (const float*)d_in[9];
    const float* bo = (const float*)d_in[10];
    float* out = (float*)d_out;

    size_t attn_smem = (size_t)((2 * 128 + QTILE) * KROW + QTILE * PROW) * sizeof(float); // ~83KB
    cudaFuncSetAttribute(attn_kernel, cudaFuncAttributeMaxDynamicSharedMemorySize,
                         (int)attn_smem);

    // 1) fused: coefficients + bias-init of all destinations (incl. d_out) + qkv expansion
    fused_prep<<<7680, 256>>>(q, k, v, wq, bq, wk, bk, wv, bv, wo, bo, out);

    // 2) q/k/v projections: K-split GEMMs, red.v2 accumulate into bias-initialized buffers
    gemm_kernel<<<dim3(8, 4, 24), 128>>>(out, 0);

    // 3) attention (128 CTAs x 16 warps, broadcast-friendly) + fused expansion into g_A[3]
    attn_kernel<<<dim3(8, HEADS, 2), 512, attn_smem>>>();

    // 4) final projection GEMM, red.v2 accumulate -> d_out
    gemm_kernel<<<dim3(8, 4, 8), 128>>>(out, 3);
}